// round 3
// baseline (speedup 1.0000x reference)
#include <cuda_runtime.h>
#include <math.h>

// Problem constants (fixed shapes from reference)
#define T_TOK 8192      // B*S tokens
#define D_DIM 2048
#define E_NUM 8
#define F_DIM 2048
#define P_MAX (T_TOK * 2)   // token-expert pairs (top-2)

// ---------------- device scratch (static; no allocations allowed) ------------
__device__ float g_h[(size_t)P_MAX * F_DIM];   // scaled hidden: w * silu(xW1^T) * (xW3^T)
__device__ int   g_pair_token[P_MAX];
__device__ float g_pair_scale[P_MAX];
__device__ int   g_counts[E_NUM];
__device__ int   g_offsets[E_NUM + 1];
__device__ int   g_cursor[E_NUM];
__device__ int   g_tok_e[T_TOK * 2];
__device__ float g_tok_w[T_TOK * 2];

// ---------------- kernel 0: zero output + counters ---------------------------
__global__ void zero_kernel(float* __restrict__ y, size_t n) {
    size_t i = (size_t)blockIdx.x * blockDim.x + threadIdx.x;
    size_t stride = (size_t)gridDim.x * blockDim.x;
    for (; i < n; i += stride) y[i] = 0.0f;
    if (blockIdx.x == 0 && threadIdx.x < E_NUM) g_counts[threadIdx.x] = 0;
}

// ---------------- kernel 1: routing (one warp per token) ---------------------
__global__ void routing_kernel(const float* __restrict__ x,
                               const float* __restrict__ gw) {
    int gwarp = (int)((blockIdx.x * blockDim.x + threadIdx.x) >> 5);
    int lane = threadIdx.x & 31;
    if (gwarp >= T_TOK) return;
    const float* xr = x + (size_t)gwarp * D_DIM;

    float acc[E_NUM];
#pragma unroll
    for (int e = 0; e < E_NUM; e++) acc[e] = 0.0f;

    for (int d = lane * 4; d < D_DIM; d += 32 * 4) {
        float4 xv = *(const float4*)(xr + d);
#pragma unroll
        for (int e = 0; e < E_NUM; e++) {
            float4 gv = *(const float4*)(gw + e * D_DIM + d);
            acc[e] += xv.x * gv.x + xv.y * gv.y + xv.z * gv.z + xv.w * gv.w;
        }
    }
#pragma unroll
    for (int e = 0; e < E_NUM; e++) {
#pragma unroll
        for (int o = 16; o; o >>= 1)
            acc[e] += __shfl_xor_sync(0xffffffffu, acc[e], o);
    }
    if (lane == 0) {
        float m = acc[0];
#pragma unroll
        for (int e = 1; e < E_NUM; e++) m = fmaxf(m, acc[e]);
        float p[E_NUM];
        float s = 0.0f;
#pragma unroll
        for (int e = 0; e < E_NUM; e++) { p[e] = expf(acc[e] - m); s += p[e]; }
        float inv = 1.0f / s;
        // top-2 (lowest index wins ties, matching jax.lax.top_k)
        int b0 = 0; float v0 = p[0];
#pragma unroll
        for (int e = 1; e < E_NUM; e++) if (p[e] > v0) { v0 = p[e]; b0 = e; }
        int b1 = -1; float v1 = -1.0f;
#pragma unroll
        for (int e = 0; e < E_NUM; e++)
            if (e != b0 && p[e] > v1) { v1 = p[e]; b1 = e; }

        g_tok_e[2 * gwarp]     = b0;  g_tok_w[2 * gwarp]     = v0 * inv;
        g_tok_e[2 * gwarp + 1] = b1;  g_tok_w[2 * gwarp + 1] = v1 * inv;
        atomicAdd(&g_counts[b0], 1);
        atomicAdd(&g_counts[b1], 1);
    }
}

// ---------------- kernel 2: exclusive scan of expert counts ------------------
__global__ void scan_kernel() {
    if (threadIdx.x == 0) {
        int s = 0;
        for (int e = 0; e < E_NUM; e++) {
            g_offsets[e] = s;
            g_cursor[e] = s;
            s += g_counts[e];
        }
        g_offsets[E_NUM] = s;
    }
}

// ---------------- kernel 3: fill per-expert pair lists -----------------------
__global__ void fill_kernel() {
    int t = blockIdx.x * blockDim.x + threadIdx.x;
    if (t >= T_TOK) return;
#pragma unroll
    for (int k = 0; k < 2; k++) {
        int e = g_tok_e[2 * t + k];
        int p = atomicAdd(&g_cursor[e], 1);
        g_pair_token[p] = t;
        g_pair_scale[p] = g_tok_w[2 * t + k];
    }
}

// ---------------- kernel 4: gate/up GEMMs + SiLU + scale ---------------------
// h[p, n] = scale[p] * silu(x[tok(p)] . w1[e,n]) * (x[tok(p)] . w3[e,n])
// 128x64 tile, 256 threads, 8x4 microtile, K-step 16.
// Padded smem strides (130/66) avoid loader store bank conflicts.
__global__ void __launch_bounds__(256, 2)
ffn_up_kernel(const float* __restrict__ x,
              const float* __restrict__ w1,
              const float* __restrict__ w3) {
    __shared__ float As[16][130];
    __shared__ float B1s[16][66];
    __shared__ float B3s[16][66];
    __shared__ int   toks[128];
    __shared__ float scl[128];

    int e = blockIdx.z;
    int start = g_offsets[e], end = g_offsets[e + 1];
    int m0 = start + blockIdx.x * 128;
    if (m0 >= end) return;

    int tid = threadIdx.x;
    if (tid < 128) {
        int p = m0 + tid;
        toks[tid] = (p < end) ? g_pair_token[p] : -1;
        scl[tid]  = (p < end) ? g_pair_scale[p] : 0.0f;
    }
    __syncthreads();

    int n0 = blockIdx.y * 64;
    int tx = tid & 15, ty = tid >> 4;
    int lrA = tid >> 1, lcA = (tid & 1) * 8;   // A loader: row 0..127, k offset 0/8
    int lrB = tid >> 2, lcB = (tid & 3) * 4;   // B loader: row 0..63,  k offset 0/4/8/12

    int tokA = toks[lrA];
    const float* xb  = (tokA >= 0) ? (x + (size_t)tokA * D_DIM) : x;
    const float* w1b = w1 + ((size_t)e * F_DIM + n0 + lrB) * D_DIM;
    const float* w3b = w3 + ((size_t)e * F_DIM + n0 + lrB) * D_DIM;

    float acc1[8][4] = {};
    float acc3[8][4] = {};

    for (int kb = 0; kb < D_DIM; kb += 16) {
        float4 a0 = make_float4(0.f, 0.f, 0.f, 0.f);
        float4 a1 = make_float4(0.f, 0.f, 0.f, 0.f);
        if (tokA >= 0) {
            a0 = *(const float4*)(xb + kb + lcA);
            a1 = *(const float4*)(xb + kb + lcA + 4);
        }
        float4 b1v = *(const float4*)(w1b + kb + lcB);
        float4 b3v = *(const float4*)(w3b + kb + lcB);

        As[lcA + 0][lrA] = a0.x; As[lcA + 1][lrA] = a0.y;
        As[lcA + 2][lrA] = a0.z; As[lcA + 3][lrA] = a0.w;
        As[lcA + 4][lrA] = a1.x; As[lcA + 5][lrA] = a1.y;
        As[lcA + 6][lrA] = a1.z; As[lcA + 7][lrA] = a1.w;
        B1s[lcB + 0][lrB] = b1v.x; B1s[lcB + 1][lrB] = b1v.y;
        B1s[lcB + 2][lrB] = b1v.z; B1s[lcB + 3][lrB] = b1v.w;
        B3s[lcB + 0][lrB] = b3v.x; B3s[lcB + 1][lrB] = b3v.y;
        B3s[lcB + 2][lrB] = b3v.z; B3s[lcB + 3][lrB] = b3v.w;
        __syncthreads();

#pragma unroll
        for (int k = 0; k < 16; k++) {
            float a[8], bf1[4], bf3[4];
#pragma unroll
            for (int i = 0; i < 8; i++) a[i] = As[k][ty + 16 * i];
#pragma unroll
            for (int j = 0; j < 4; j++) { bf1[j] = B1s[k][tx + 16 * j]; bf3[j] = B3s[k][tx + 16 * j]; }
#pragma unroll
            for (int i = 0; i < 8; i++)
#pragma unroll
                for (int j = 0; j < 4; j++) {
                    acc1[i][j] += a[i] * bf1[j];
                    acc3[i][j] += a[i] * bf3[j];
                }
        }
        __syncthreads();
    }

#pragma unroll
    for (int i = 0; i < 8; i++) {
        int rl = ty + 16 * i;
        int p = m0 + rl;
        if (p < end) {
            float s = scl[rl];
            float* hb = g_h + (size_t)p * F_DIM + n0;
#pragma unroll
            for (int j = 0; j < 4; j++) {
                float g = acc1[i][j];
                float u = acc3[i][j];
                hb[tx + 16 * j] = (g / (1.0f + expf(-g))) * u * s;
            }
        }
    }
}

// ---------------- kernel 5: down projection + scatter-add --------------------
// y[tok(p), d] += h[p] . w2[e, d, :]
__global__ void __launch_bounds__(256, 2)
down_kernel(const float* __restrict__ w2, float* __restrict__ y) {
    __shared__ float As[16][130];
    __shared__ float Bs[16][66];
    __shared__ int   toks[128];

    int e = blockIdx.z;
    int start = g_offsets[e], end = g_offsets[e + 1];
    int m0 = start + blockIdx.x * 128;
    if (m0 >= end) return;

    int tid = threadIdx.x;
    if (tid < 128) {
        int p = m0 + tid;
        toks[tid] = (p < end) ? g_pair_token[p] : -1;
    }
    __syncthreads();

    int n0 = blockIdx.y * 64;           // over D
    int tx = tid & 15, ty = tid >> 4;
    int lrA = tid >> 1, lcA = (tid & 1) * 8;
    int lrB = tid >> 2, lcB = (tid & 3) * 4;

    bool rvalid = (m0 + lrA) < end;
    const float* hb  = g_h + (size_t)(rvalid ? (m0 + lrA) : 0) * F_DIM;
    const float* w2b = w2 + ((size_t)e * D_DIM + n0 + lrB) * F_DIM;

    float acc[8][4] = {};

    for (int kb = 0; kb < F_DIM; kb += 16) {
        float4 a0 = make_float4(0.f, 0.f, 0.f, 0.f);
        float4 a1 = make_float4(0.f, 0.f, 0.f, 0.f);
        if (rvalid) {
            a0 = *(const float4*)(hb + kb + lcA);
            a1 = *(const float4*)(hb + kb + lcA + 4);
        }
        float4 bv = *(const float4*)(w2b + kb + lcB);

        As[lcA + 0][lrA] = a0.x; As[lcA + 1][lrA] = a0.y;
        As[lcA + 2][lrA] = a0.z; As[lcA + 3][lrA] = a0.w;
        As[lcA + 4][lrA] = a1.x; As[lcA + 5][lrA] = a1.y;
        As[lcA + 6][lrA] = a1.z; As[lcA + 7][lrA] = a1.w;
        Bs[lcB + 0][lrB] = bv.x; Bs[lcB + 1][lrB] = bv.y;
        Bs[lcB + 2][lrB] = bv.z; Bs[lcB + 3][lrB] = bv.w;
        __syncthreads();

#pragma unroll
        for (int k = 0; k < 16; k++) {
            float a[8], bf[4];
#pragma unroll
            for (int i = 0; i < 8; i++) a[i] = As[k][ty + 16 * i];
#pragma unroll
            for (int j = 0; j < 4; j++) bf[j] = Bs[k][tx + 16 * j];
#pragma unroll
            for (int i = 0; i < 8; i++)
#pragma unroll
                for (int j = 0; j < 4; j++)
                    acc[i][j] += a[i] * bf[j];
        }
        __syncthreads();
    }

#pragma unroll
    for (int i = 0; i < 8; i++) {
        int rl = ty + 16 * i;
        if (m0 + rl < end) {
            int tok = toks[rl];
            float* yb = y + (size_t)tok * D_DIM + n0;
#pragma unroll
            for (int j = 0; j < 4; j++)
                atomicAdd(&yb[tx + 16 * j], acc[i][j]);
        }
    }
}

// ---------------- launch ------------------------------------------------------
extern "C" void kernel_launch(void* const* d_in, const int* in_sizes, int n_in,
                              void* d_out, int out_size) {
    const float* x  = (const float*)d_in[0];
    const float* gw = (const float*)d_in[1];
    const float* w1 = (const float*)d_in[2];
    const float* w3 = (const float*)d_in[3];
    const float* w2 = (const float*)d_in[4];
    float* y = (float*)d_out;

    zero_kernel<<<4096, 256>>>(y, (size_t)T_TOK * D_DIM);
    routing_kernel<<<T_TOK / 8, 256>>>(x, gw);
    scan_kernel<<<1, 32>>>();
    fill_kernel<<<T_TOK / 256, 256>>>();

    dim3 gA(P_MAX / 128, F_DIM / 64, E_NUM);   // 128 x 32 x 8 (early-exit past expert end)
    ffn_up_kernel<<<gA, 256>>>(x, w1, w3);

    dim3 gB(P_MAX / 128, D_DIM / 64, E_NUM);
    down_kernel<<<gB, 256>>>(w2, y);
}

// round 5
// speedup vs baseline: 1.6265x; 1.6265x over previous
#include <cuda_runtime.h>
#include <cuda_bf16.h>
#include <math.h>
#include <stdint.h>

// Problem constants (fixed shapes from reference)
#define T_TOK 8192      // B*S tokens
#define D_DIM 2048
#define E_NUM 8
#define F_DIM 2048
#define P_MAX (T_TOK * 2)   // token-expert pairs (top-2)

// ---------------- device scratch (static; no allocations allowed) ------------
__device__ float g_h[(size_t)P_MAX * F_DIM];   // scaled hidden
__device__ int   g_pair_token[P_MAX];
__device__ float g_pair_scale[P_MAX];
__device__ int   g_counts[E_NUM];
__device__ int   g_offsets[E_NUM + 1];
__device__ int   g_cursor[E_NUM];
__device__ int   g_tok_e[T_TOK * 2];
__device__ float g_tok_w[T_TOK * 2];

// ---------------- helpers -----------------------------------------------------
// bf16 mma, m16n8k16, fp32 accumulate
__device__ __forceinline__ void mma_bf16(float* c,
                                         uint32_t a0, uint32_t a1, uint32_t a2, uint32_t a3,
                                         uint32_t b0, uint32_t b1) {
    asm volatile(
        "mma.sync.aligned.m16n8k16.row.col.f32.bf16.bf16.f32 "
        "{%0,%1,%2,%3}, {%4,%5,%6,%7}, {%8,%9}, {%0,%1,%2,%3};"
        : "+f"(c[0]), "+f"(c[1]), "+f"(c[2]), "+f"(c[3])
        : "r"(a0), "r"(a1), "r"(a2), "r"(a3), "r"(b0), "r"(b1));
}

// split two consecutive fp32 values into packed bf16 hi and lo residual pairs
__device__ __forceinline__ void split2(float x0, float x1, uint32_t& hi, uint32_t& lo) {
    __nv_bfloat16 h0 = __float2bfloat16(x0);
    __nv_bfloat16 h1 = __float2bfloat16(x1);
    __nv_bfloat16 l0 = __float2bfloat16(x0 - __bfloat162float(h0));
    __nv_bfloat16 l1 = __float2bfloat16(x1 - __bfloat162float(h1));
    hi = (uint32_t)__bfloat16_as_ushort(h0) | ((uint32_t)__bfloat16_as_ushort(h1) << 16);
    lo = (uint32_t)__bfloat16_as_ushort(l0) | ((uint32_t)__bfloat16_as_ushort(l1) << 16);
}

// ---------------- kernel 0: zero output + counters ---------------------------
__global__ void zero_kernel(float* __restrict__ y, size_t n) {
    size_t i = (size_t)blockIdx.x * blockDim.x + threadIdx.x;
    size_t stride = (size_t)gridDim.x * blockDim.x;
    for (; i < n; i += stride) y[i] = 0.0f;
    if (blockIdx.x == 0 && threadIdx.x < E_NUM) g_counts[threadIdx.x] = 0;
}

// ---------------- kernel 1: routing (one warp per token) ---------------------
__global__ void routing_kernel(const float* __restrict__ x,
                               const float* __restrict__ gw) {
    int gwarp = (int)((blockIdx.x * blockDim.x + threadIdx.x) >> 5);
    int lane = threadIdx.x & 31;
    if (gwarp >= T_TOK) return;
    const float* xr = x + (size_t)gwarp * D_DIM;

    float acc[E_NUM];
#pragma unroll
    for (int e = 0; e < E_NUM; e++) acc[e] = 0.0f;

    for (int d = lane * 4; d < D_DIM; d += 32 * 4) {
        float4 xv = *(const float4*)(xr + d);
#pragma unroll
        for (int e = 0; e < E_NUM; e++) {
            float4 gv = *(const float4*)(gw + e * D_DIM + d);
            acc[e] += xv.x * gv.x + xv.y * gv.y + xv.z * gv.z + xv.w * gv.w;
        }
    }
#pragma unroll
    for (int e = 0; e < E_NUM; e++) {
#pragma unroll
        for (int o = 16; o; o >>= 1)
            acc[e] += __shfl_xor_sync(0xffffffffu, acc[e], o);
    }
    if (lane == 0) {
        float m = acc[0];
#pragma unroll
        for (int e = 1; e < E_NUM; e++) m = fmaxf(m, acc[e]);
        float p[E_NUM];
        float s = 0.0f;
#pragma unroll
        for (int e = 0; e < E_NUM; e++) { p[e] = expf(acc[e] - m); s += p[e]; }
        float inv = 1.0f / s;
        int b0 = 0; float v0 = p[0];
#pragma unroll
        for (int e = 1; e < E_NUM; e++) if (p[e] > v0) { v0 = p[e]; b0 = e; }
        int b1 = -1; float v1 = -1.0f;
#pragma unroll
        for (int e = 0; e < E_NUM; e++)
            if (e != b0 && p[e] > v1) { v1 = p[e]; b1 = e; }

        g_tok_e[2 * gwarp]     = b0;  g_tok_w[2 * gwarp]     = v0 * inv;
        g_tok_e[2 * gwarp + 1] = b1;  g_tok_w[2 * gwarp + 1] = v1 * inv;
        atomicAdd(&g_counts[b0], 1);
        atomicAdd(&g_counts[b1], 1);
    }
}

// ---------------- kernel 2: exclusive scan of expert counts ------------------
__global__ void scan_kernel() {
    if (threadIdx.x == 0) {
        int s = 0;
        for (int e = 0; e < E_NUM; e++) {
            g_offsets[e] = s;
            g_cursor[e] = s;
            s += g_counts[e];
        }
        g_offsets[E_NUM] = s;
    }
}

// ---------------- kernel 3: fill per-expert pair lists -----------------------
__global__ void fill_kernel() {
    int t = blockIdx.x * blockDim.x + threadIdx.x;
    if (t >= T_TOK) return;
#pragma unroll
    for (int k = 0; k < 2; k++) {
        int e = g_tok_e[2 * t + k];
        int p = atomicAdd(&g_cursor[e], 1);
        g_pair_token[p] = t;
        g_pair_scale[p] = g_tok_w[2 * t + k];
    }
}

// ---------------- kernel 4: gate/up GEMMs + SiLU + scale (bf16-split mma) ----
// Block: 128(M pairs) x 64(N). 8 warps 2x4; warp tile 64x16.
// K-step 32 (two m16n8k16 substeps). smem rows hold 16 packed bf16x2 words,
// padded stride 20 words (conflict-free: 20*r mod 32 over r=0..7 + q=0..3
// covers all 32 banks exactly once).
#define AW 20

__global__ void __launch_bounds__(256)
ffn_up_kernel(const float* __restrict__ x,
              const float* __restrict__ w1,
              const float* __restrict__ w3) {
    __shared__ uint32_t Ah[128][AW], Al[128][AW];
    __shared__ uint32_t B1h[64][AW], B1l[64][AW];
    __shared__ uint32_t B3h[64][AW], B3l[64][AW];
    __shared__ int   toks[128];
    __shared__ float scl[128];

    int e = blockIdx.z;
    int start = g_offsets[e], end = g_offsets[e + 1];
    int m0 = start + blockIdx.x * 128;
    if (m0 >= end) return;

    int tid = threadIdx.x;
    if (tid < 128) {
        int p = m0 + tid;
        toks[tid] = (p < end) ? g_pair_token[p] : -1;
        scl[tid]  = (p < end) ? g_pair_scale[p] : 0.0f;
    }
    __syncthreads();

    int n0 = blockIdx.y * 64;
    int lane = tid & 31, wid = tid >> 5;
    int g = lane >> 2, t = lane & 3;
    int rowBase = (wid & 1) * 64;
    int colBase = (wid >> 1) * 16;

    // loaders: A 128 rows x 32 floats (2 threads/row, 16 floats each)
    //          B 64 rows x 32 floats (4 threads/row, 8 floats each)
    int lrA = tid >> 1, kaA = (tid & 1) * 16;
    int lrB = tid >> 2, kaB = (tid & 3) * 8;

    int tokA = toks[lrA];
    const float* xb  = (tokA >= 0) ? (x + (size_t)tokA * D_DIM) : x;
    const float* w1b = w1 + ((size_t)e * F_DIM + n0 + lrB) * D_DIM;
    const float* w3b = w3 + ((size_t)e * F_DIM + n0 + lrB) * D_DIM;

    float c1v[4][2][4] = {};
    float c3v[4][2][4] = {};

    float pa[16], pb1[8], pb3[8];
    // prefetch kb = 0
    {
#pragma unroll
        for (int q = 0; q < 4; q++) {
            float4 v = (tokA >= 0) ? *(const float4*)(xb + kaA + 4 * q)
                                   : make_float4(0.f, 0.f, 0.f, 0.f);
            pa[4*q] = v.x; pa[4*q+1] = v.y; pa[4*q+2] = v.z; pa[4*q+3] = v.w;
        }
#pragma unroll
        for (int q = 0; q < 2; q++) {
            float4 v1 = *(const float4*)(w1b + kaB + 4 * q);
            float4 v3 = *(const float4*)(w3b + kaB + 4 * q);
            pb1[4*q]=v1.x; pb1[4*q+1]=v1.y; pb1[4*q+2]=v1.z; pb1[4*q+3]=v1.w;
            pb3[4*q]=v3.x; pb3[4*q+1]=v3.y; pb3[4*q+2]=v3.z; pb3[4*q+3]=v3.w;
        }
    }

    for (int kb = 0; kb < D_DIM; kb += 32) {
        // split + stage into smem
        int wA = kaA >> 1;   // word offset 0 or 8
        int wB = kaB >> 1;   // word offset 0,4,8,12
#pragma unroll
        for (int i = 0; i < 8; i++) {
            uint32_t hi, lo;
            split2(pa[2*i], pa[2*i+1], hi, lo);
            Ah[lrA][wA + i] = hi; Al[lrA][wA + i] = lo;
        }
#pragma unroll
        for (int i = 0; i < 4; i++) {
            uint32_t hi, lo;
            split2(pb1[2*i], pb1[2*i+1], hi, lo);
            B1h[lrB][wB + i] = hi; B1l[lrB][wB + i] = lo;
            split2(pb3[2*i], pb3[2*i+1], hi, lo);
            B3h[lrB][wB + i] = hi; B3l[lrB][wB + i] = lo;
        }
        __syncthreads();

        // prefetch next K-tile (overlaps mma)
        if (kb + 32 < D_DIM) {
            int kn = kb + 32;
#pragma unroll
            for (int q = 0; q < 4; q++) {
                float4 v = (tokA >= 0) ? *(const float4*)(xb + kn + kaA + 4 * q)
                                       : make_float4(0.f, 0.f, 0.f, 0.f);
                pa[4*q] = v.x; pa[4*q+1] = v.y; pa[4*q+2] = v.z; pa[4*q+3] = v.w;
            }
#pragma unroll
            for (int q = 0; q < 2; q++) {
                float4 v1 = *(const float4*)(w1b + kn + kaB + 4 * q);
                float4 v3 = *(const float4*)(w3b + kn + kaB + 4 * q);
                pb1[4*q]=v1.x; pb1[4*q+1]=v1.y; pb1[4*q+2]=v1.z; pb1[4*q+3]=v1.w;
                pb3[4*q]=v3.x; pb3[4*q+1]=v3.y; pb3[4*q+2]=v3.z; pb3[4*q+3]=v3.w;
            }
        }

        // two k16 substeps: packed-word base q0 = 0, 8
#pragma unroll
        for (int q0 = 0; q0 < 16; q0 += 8) {
            uint32_t ah[4][4], al[4][4];
#pragma unroll
            for (int i = 0; i < 4; i++) {
                int r = rowBase + i * 16 + g;
                ah[i][0] = Ah[r][q0 + t];     ah[i][1] = Ah[r + 8][q0 + t];
                ah[i][2] = Ah[r][q0 + t + 4]; ah[i][3] = Ah[r + 8][q0 + t + 4];
                al[i][0] = Al[r][q0 + t];     al[i][1] = Al[r + 8][q0 + t];
                al[i][2] = Al[r][q0 + t + 4]; al[i][3] = Al[r + 8][q0 + t + 4];
            }
#pragma unroll
            for (int j = 0; j < 2; j++) {
                int n = colBase + j * 8 + g;
                uint32_t b1h0 = B1h[n][q0 + t], b1h1 = B1h[n][q0 + t + 4];
                uint32_t b1l0 = B1l[n][q0 + t], b1l1 = B1l[n][q0 + t + 4];
                uint32_t b3h0 = B3h[n][q0 + t], b3h1 = B3h[n][q0 + t + 4];
                uint32_t b3l0 = B3l[n][q0 + t], b3l1 = B3l[n][q0 + t + 4];
#pragma unroll
                for (int i = 0; i < 4; i++) {
                    mma_bf16(c1v[i][j], ah[i][0], ah[i][1], ah[i][2], ah[i][3], b1h0, b1h1);
                    mma_bf16(c1v[i][j], ah[i][0], ah[i][1], ah[i][2], ah[i][3], b1l0, b1l1);
                    mma_bf16(c1v[i][j], al[i][0], al[i][1], al[i][2], al[i][3], b1h0, b1h1);
                    mma_bf16(c3v[i][j], ah[i][0], ah[i][1], ah[i][2], ah[i][3], b3h0, b3h1);
                    mma_bf16(c3v[i][j], ah[i][0], ah[i][1], ah[i][2], ah[i][3], b3l0, b3l1);
                    mma_bf16(c3v[i][j], al[i][0], al[i][1], al[i][2], al[i][3], b3h0, b3h1);
                }
            }
        }
        __syncthreads();
    }

    // epilogue: silu(gate) * up * routing_scale -> g_h
#pragma unroll
    for (int i = 0; i < 4; i++) {
#pragma unroll
        for (int j = 0; j < 2; j++) {
            int col = n0 + colBase + j * 8 + 2 * t;
#pragma unroll
            for (int h = 0; h < 2; h++) {
                int rl = rowBase + i * 16 + g + h * 8;
                int p = m0 + rl;
                if (p < end) {
                    float s = scl[rl];
                    float gg0 = c1v[i][j][2 * h + 0], uu0 = c3v[i][j][2 * h + 0];
                    float gg1 = c1v[i][j][2 * h + 1], uu1 = c3v[i][j][2 * h + 1];
                    float* hb = g_h + (size_t)p * F_DIM;
                    hb[col]     = (gg0 / (1.0f + expf(-gg0))) * uu0 * s;
                    hb[col + 1] = (gg1 / (1.0f + expf(-gg1))) * uu1 * s;
                }
            }
        }
    }
}

// ---------------- kernel 5: down projection + scatter-add (bf16-split mma) ---
__global__ void __launch_bounds__(256)
down_kernel(const float* __restrict__ w2, float* __restrict__ y) {
    __shared__ uint32_t Ah[128][AW], Al[128][AW];
    __shared__ uint32_t Bh[64][AW], Bl[64][AW];
    __shared__ int toks[128];

    int e = blockIdx.z;
    int start = g_offsets[e], end = g_offsets[e + 1];
    int m0 = start + blockIdx.x * 128;
    if (m0 >= end) return;

    int tid = threadIdx.x;
    if (tid < 128) {
        int p = m0 + tid;
        toks[tid] = (p < end) ? g_pair_token[p] : -1;
    }
    __syncthreads();

    int n0 = blockIdx.y * 64;
    int lane = tid & 31, wid = tid >> 5;
    int g = lane >> 2, t = lane & 3;
    int rowBase = (wid & 1) * 64;
    int colBase = (wid >> 1) * 16;

    int lrA = tid >> 1, kaA = (tid & 1) * 16;
    int lrB = tid >> 2, kaB = (tid & 3) * 8;

    bool rvalid = (m0 + lrA) < end;
    const float* hb  = g_h + (size_t)(rvalid ? (m0 + lrA) : 0) * F_DIM;
    const float* w2b = w2 + ((size_t)e * D_DIM + n0 + lrB) * F_DIM;

    float cv[4][2][4] = {};

    float pa[16], pb[8];
    {
#pragma unroll
        for (int q = 0; q < 4; q++) {
            float4 v = rvalid ? *(const float4*)(hb + kaA + 4 * q)
                              : make_float4(0.f, 0.f, 0.f, 0.f);
            pa[4*q] = v.x; pa[4*q+1] = v.y; pa[4*q+2] = v.z; pa[4*q+3] = v.w;
        }
#pragma unroll
        for (int q = 0; q < 2; q++) {
            float4 v = *(const float4*)(w2b + kaB + 4 * q);
            pb[4*q]=v.x; pb[4*q+1]=v.y; pb[4*q+2]=v.z; pb[4*q+3]=v.w;
        }
    }

    for (int kb = 0; kb < F_DIM; kb += 32) {
        int wA = kaA >> 1;
        int wB = kaB >> 1;
#pragma unroll
        for (int i = 0; i < 8; i++) {
            uint32_t hi, lo;
            split2(pa[2*i], pa[2*i+1], hi, lo);
            Ah[lrA][wA + i] = hi; Al[lrA][wA + i] = lo;
        }
#pragma unroll
        for (int i = 0; i < 4; i++) {
            uint32_t hi, lo;
            split2(pb[2*i], pb[2*i+1], hi, lo);
            Bh[lrB][wB + i] = hi; Bl[lrB][wB + i] = lo;
        }
        __syncthreads();

        if (kb + 32 < F_DIM) {
            int kn = kb + 32;
#pragma unroll
            for (int q = 0; q < 4; q++) {
                float4 v = rvalid ? *(const float4*)(hb + kn + kaA + 4 * q)
                                  : make_float4(0.f, 0.f, 0.f, 0.f);
                pa[4*q] = v.x; pa[4*q+1] = v.y; pa[4*q+2] = v.z; pa[4*q+3] = v.w;
            }
#pragma unroll
            for (int q = 0; q < 2; q++) {
                float4 v = *(const float4*)(w2b + kn + kaB + 4 * q);
                pb[4*q]=v.x; pb[4*q+1]=v.y; pb[4*q+2]=v.z; pb[4*q+3]=v.w;
            }
        }

#pragma unroll
        for (int q0 = 0; q0 < 16; q0 += 8) {
            uint32_t ah[4][4], al[4][4];
#pragma unroll
            for (int i = 0; i < 4; i++) {
                int r = rowBase + i * 16 + g;
                ah[i][0] = Ah[r][q0 + t];     ah[i][1] = Ah[r + 8][q0 + t];
                ah[i][2] = Ah[r][q0 + t + 4]; ah[i][3] = Ah[r + 8][q0 + t + 4];
                al[i][0] = Al[r][q0 + t];     al[i][1] = Al[r + 8][q0 + t];
                al[i][2] = Al[r][q0 + t + 4]; al[i][3] = Al[r + 8][q0 + t + 4];
            }
#pragma unroll
            for (int j = 0; j < 2; j++) {
                int n = colBase + j * 8 + g;
                uint32_t bh0 = Bh[n][q0 + t], bh1 = Bh[n][q0 + t + 4];
                uint32_t bl0 = Bl[n][q0 + t], bl1 = Bl[n][q0 + t + 4];
#pragma unroll
                for (int i = 0; i < 4; i++) {
                    mma_bf16(cv[i][j], ah[i][0], ah[i][1], ah[i][2], ah[i][3], bh0, bh1);
                    mma_bf16(cv[i][j], ah[i][0], ah[i][1], ah[i][2], ah[i][3], bl0, bl1);
                    mma_bf16(cv[i][j], al[i][0], al[i][1], al[i][2], al[i][3], bh0, bh1);
                }
            }
        }
        __syncthreads();
    }

    // epilogue: scatter-add into y
#pragma unroll
    for (int i = 0; i < 4; i++) {
#pragma unroll
        for (int j = 0; j < 2; j++) {
            int col = n0 + colBase + j * 8 + 2 * t;
#pragma unroll
            for (int h = 0; h < 2; h++) {
                int rl = rowBase + i * 16 + g + h * 8;
                if (m0 + rl < end) {
                    int tok = toks[rl];
                    float* yb = y + (size_t)tok * D_DIM;
                    atomicAdd(&yb[col],     cv[i][j][2 * h + 0]);
                    atomicAdd(&yb[col + 1], cv[i][j][2 * h + 1]);
                }
            }
        }
    }
}

// ---------------- launch ------------------------------------------------------
extern "C" void kernel_launch(void* const* d_in, const int* in_sizes, int n_in,
                              void* d_out, int out_size) {
    const float* x  = (const float*)d_in[0];
    const float* gw = (const float*)d_in[1];
    const float* w1 = (const float*)d_in[2];
    const float* w3 = (const float*)d_in[3];
    const float* w2 = (const float*)d_in[4];
    float* y = (float*)d_out;

    zero_kernel<<<4096, 256>>>(y, (size_t)T_TOK * D_DIM);
    routing_kernel<<<T_TOK / 8, 256>>>(x, gw);
    scan_kernel<<<1, 32>>>();
    fill_kernel<<<T_TOK / 256, 256>>>();

    dim3 gA(P_MAX / 128, F_DIM / 64, E_NUM);
    ffn_up_kernel<<<gA, 256>>>(x, w1, w3);

    dim3 gB(P_MAX / 128, D_DIM / 64, E_NUM);
    down_kernel<<<gB, 256>>>(w2, y);
}

// round 9
// speedup vs baseline: 1.9201x; 1.1805x over previous
#include <cuda_runtime.h>
#include <cuda_bf16.h>
#include <math.h>
#include <stdint.h>

// Problem constants (fixed shapes from reference)
#define T_TOK 8192      // B*S tokens
#define D_DIM 2048
#define E_NUM 8
#define F_DIM 2048
#define P_MAX (T_TOK * 2)   // token-expert pairs (top-2)

// ---------------- device scratch (static; no allocations allowed) ------------
__device__ float g_h[(size_t)P_MAX * F_DIM];   // scaled hidden
__device__ int   g_pair_token[P_MAX];
__device__ float g_pair_scale[P_MAX];
__device__ int   g_counts[E_NUM];
__device__ int   g_offsets[E_NUM + 1];
__device__ int   g_cursor[E_NUM];
__device__ int   g_tok_e[T_TOK * 2];
__device__ float g_tok_w[T_TOK * 2];

// ---------------- helpers -----------------------------------------------------
__device__ __forceinline__ void mma_bf16(float* c,
                                         uint32_t a0, uint32_t a1, uint32_t a2, uint32_t a3,
                                         uint32_t b0, uint32_t b1) {
    asm volatile(
        "mma.sync.aligned.m16n8k16.row.col.f32.bf16.bf16.f32 "
        "{%0,%1,%2,%3}, {%4,%5,%6,%7}, {%8,%9}, {%0,%1,%2,%3};"
        : "+f"(c[0]), "+f"(c[1]), "+f"(c[2]), "+f"(c[3])
        : "r"(a0), "r"(a1), "r"(a2), "r"(a3), "r"(b0), "r"(b1));
}

__device__ __forceinline__ void ldsm4(uint32_t& d0, uint32_t& d1, uint32_t& d2, uint32_t& d3,
                                      uint32_t addr) {
    asm volatile("ldmatrix.sync.aligned.m8n8.x4.shared.b16 {%0,%1,%2,%3}, [%4];"
                 : "=r"(d0), "=r"(d1), "=r"(d2), "=r"(d3) : "r"(addr));
}

__device__ __forceinline__ void split2(float x0, float x1, uint32_t& hi, uint32_t& lo) {
    __nv_bfloat16 h0 = __float2bfloat16(x0);
    __nv_bfloat16 h1 = __float2bfloat16(x1);
    __nv_bfloat16 l0 = __float2bfloat16(x0 - __bfloat162float(h0));
    __nv_bfloat16 l1 = __float2bfloat16(x1 - __bfloat162float(h1));
    hi = (uint32_t)__bfloat16_as_ushort(h0) | ((uint32_t)__bfloat16_as_ushort(h1) << 16);
    lo = (uint32_t)__bfloat16_as_ushort(l0) | ((uint32_t)__bfloat16_as_ushort(l1) << 16);
}

__device__ __forceinline__ uint32_t cvs(const void* p) {
    return (uint32_t)__cvta_generic_to_shared(p);
}

// smem geometry: rows of 8 bf16x2 words (k16), padded stride 12 words.
// LDSM 8-row phases -> banks {12r mod 32} + 4-word chunk: conflict-free.
#define RW 12
#define A_STG (128 * RW)   // words per A stage
#define B_STG (64 * RW)    // words per B stage

// ---------------- kernel 0: zero output + counters ---------------------------
__global__ void zero_kernel(float* __restrict__ y, size_t n) {
    size_t i = (size_t)blockIdx.x * blockDim.x + threadIdx.x;
    size_t stride = (size_t)gridDim.x * blockDim.x;
    for (; i < n; i += stride) y[i] = 0.0f;
    if (blockIdx.x == 0 && threadIdx.x < E_NUM) g_counts[threadIdx.x] = 0;
}

// ---------------- kernel 1: routing (one warp per token) ---------------------
__global__ void routing_kernel(const float* __restrict__ x,
                               const float* __restrict__ gw) {
    int gwarp = (int)((blockIdx.x * blockDim.x + threadIdx.x) >> 5);
    int lane = threadIdx.x & 31;
    if (gwarp >= T_TOK) return;
    const float* xr = x + (size_t)gwarp * D_DIM;

    float acc[E_NUM];
#pragma unroll
    for (int e = 0; e < E_NUM; e++) acc[e] = 0.0f;

    for (int d = lane * 4; d < D_DIM; d += 32 * 4) {
        float4 xv = *(const float4*)(xr + d);
#pragma unroll
        for (int e = 0; e < E_NUM; e++) {
            float4 gv = *(const float4*)(gw + e * D_DIM + d);
            acc[e] += xv.x * gv.x + xv.y * gv.y + xv.z * gv.z + xv.w * gv.w;
        }
    }
#pragma unroll
    for (int e = 0; e < E_NUM; e++) {
#pragma unroll
        for (int o = 16; o; o >>= 1)
            acc[e] += __shfl_xor_sync(0xffffffffu, acc[e], o);
    }
    if (lane == 0) {
        float m = acc[0];
#pragma unroll
        for (int e = 1; e < E_NUM; e++) m = fmaxf(m, acc[e]);
        float p[E_NUM];
        float s = 0.0f;
#pragma unroll
        for (int e = 0; e < E_NUM; e++) { p[e] = expf(acc[e] - m); s += p[e]; }
        float inv = 1.0f / s;
        int b0 = 0; float v0 = p[0];
#pragma unroll
        for (int e = 1; e < E_NUM; e++) if (p[e] > v0) { v0 = p[e]; b0 = e; }
        int b1 = -1; float v1 = -1.0f;
#pragma unroll
        for (int e = 0; e < E_NUM; e++)
            if (e != b0 && p[e] > v1) { v1 = p[e]; b1 = e; }

        g_tok_e[2 * gwarp]     = b0;  g_tok_w[2 * gwarp]     = v0 * inv;
        g_tok_e[2 * gwarp + 1] = b1;  g_tok_w[2 * gwarp + 1] = v1 * inv;
        atomicAdd(&g_counts[b0], 1);
        atomicAdd(&g_counts[b1], 1);
    }
}

// ---------------- kernel 2: exclusive scan of expert counts ------------------
__global__ void scan_kernel() {
    if (threadIdx.x == 0) {
        int s = 0;
        for (int e = 0; e < E_NUM; e++) {
            g_offsets[e] = s;
            g_cursor[e] = s;
            s += g_counts[e];
        }
        g_offsets[E_NUM] = s;
    }
}

// ---------------- kernel 3: fill per-expert pair lists -----------------------
__global__ void fill_kernel() {
    int t = blockIdx.x * blockDim.x + threadIdx.x;
    if (t >= T_TOK) return;
#pragma unroll
    for (int k = 0; k < 2; k++) {
        int e = g_tok_e[2 * t + k];
        int p = atomicAdd(&g_cursor[e], 1);
        g_pair_token[p] = t;
        g_pair_scale[p] = g_tok_w[2 * t + k];
    }
}

// ---------------- kernel 4: gate/up GEMMs + SiLU + scale ---------------------
// bf16-split (3-term) mma, ldmatrix fragments, double-buffered K16 stages.
// Block 128(M) x 64(N), 8 warps 2x4, warp tile 64x16.
__global__ void __launch_bounds__(256)
ffn_up_kernel(const float* __restrict__ x,
              const float* __restrict__ w1,
              const float* __restrict__ w3) {
    extern __shared__ uint32_t sm[];
    uint32_t* Ah  = sm;                   // [2][128][RW]
    uint32_t* Al  = Ah + 2 * A_STG;
    uint32_t* B1h = Al + 2 * A_STG;       // [2][64][RW]
    uint32_t* B1l = B1h + 2 * B_STG;
    uint32_t* B3h = B1l + 2 * B_STG;
    uint32_t* B3l = B3h + 2 * B_STG;
    __shared__ int   toks[128];
    __shared__ float scl[128];

    int e = blockIdx.z;
    int start = g_offsets[e], end = g_offsets[e + 1];
    int m0 = start + blockIdx.x * 128;
    if (m0 >= end) return;

    int tid = threadIdx.x;
    if (tid < 128) {
        int p = m0 + tid;
        toks[tid] = (p < end) ? g_pair_token[p] : -1;
        scl[tid]  = (p < end) ? g_pair_scale[p] : 0.0f;
    }
    __syncthreads();

    int n0 = blockIdx.y * 64;
    int lane = tid & 31, wid = tid >> 5;
    int g = lane >> 2, t = lane & 3;
    int rowBase = (wid & 1) * 64;
    int colBase = (wid >> 1) * 16;

    // loaders: A 128 rows x 16 floats (2 thr/row, 8 floats), B 64 rows x 16 (4 thr/row, 4 floats)
    int lrA = tid >> 1, kaA = (tid & 1) * 8, wA = (tid & 1) * 4;
    int lrB = tid >> 2, kaB = (tid & 3) * 4, wB = (tid & 3) * 2;

    int tokA = toks[lrA];
    const float* xb  = (tokA >= 0) ? (x + (size_t)tokA * D_DIM) : x;
    const float* w1b = w1 + ((size_t)e * F_DIM + n0 + lrB) * D_DIM;
    const float* w3b = w3 + ((size_t)e * F_DIM + n0 + lrB) * D_DIM;

    // ldmatrix byte-address geometry (per lane)
    uint32_t cvAh = cvs(Ah), cvAl = cvs(Al);
    uint32_t cvB1h = cvs(B1h), cvB1l = cvs(B1l);
    uint32_t cvB3h = cvs(B3h), cvB3l = cvs(B3l);
    int offA[4];
#pragma unroll
    for (int i = 0; i < 4; i++)
        offA[i] = ((rowBase + i * 16 + (lane & 15)) * RW + (lane >> 4) * 4) * 4;
    int offB[2];
#pragma unroll
    for (int j = 0; j < 2; j++)
        offB[j] = ((colBase + j * 8 + (lane & 7)) * RW + ((lane >> 3) & 1) * 4) * 4;
    bool hsel = lane < 16;     // lanes 0-15 read hi array, 16-31 read lo array
    uint32_t bB1 = (hsel ? cvB1h : cvB1l);
    uint32_t bB3 = (hsel ? cvB3h : cvB3l);

    float c1v[4][2][4] = {};
    float c3v[4][2][4] = {};

    float pa[8], pb1[4], pb3[4];

#define LOADREG_UP(KB) do {                                                     \
        float4 v0 = (tokA >= 0) ? *(const float4*)(xb + (KB) + kaA)             \
                                : make_float4(0.f, 0.f, 0.f, 0.f);              \
        float4 v1 = (tokA >= 0) ? *(const float4*)(xb + (KB) + kaA + 4)         \
                                : make_float4(0.f, 0.f, 0.f, 0.f);              \
        pa[0]=v0.x; pa[1]=v0.y; pa[2]=v0.z; pa[3]=v0.w;                         \
        pa[4]=v1.x; pa[5]=v1.y; pa[6]=v1.z; pa[7]=v1.w;                         \
        float4 u1 = *(const float4*)(w1b + (KB) + kaB);                         \
        float4 u3 = *(const float4*)(w3b + (KB) + kaB);                         \
        pb1[0]=u1.x; pb1[1]=u1.y; pb1[2]=u1.z; pb1[3]=u1.w;                     \
        pb3[0]=u3.x; pb3[1]=u3.y; pb3[2]=u3.z; pb3[3]=u3.w;                     \
    } while (0)

#define STORE_UP(S) do {                                                        \
        uint32_t h[4], l[4];                                                    \
        split2(pa[0], pa[1], h[0], l[0]); split2(pa[2], pa[3], h[1], l[1]);     \
        split2(pa[4], pa[5], h[2], l[2]); split2(pa[6], pa[7], h[3], l[3]);     \
        *(uint4*)(Ah + (S) * A_STG + lrA * RW + wA) = make_uint4(h[0],h[1],h[2],h[3]); \
        *(uint4*)(Al + (S) * A_STG + lrA * RW + wA) = make_uint4(l[0],l[1],l[2],l[3]); \
        uint32_t bh0, bl0, bh1, bl1;                                            \
        split2(pb1[0], pb1[1], bh0, bl0); split2(pb1[2], pb1[3], bh1, bl1);     \
        *(uint2*)(B1h + (S) * B_STG + lrB * RW + wB) = make_uint2(bh0, bh1);    \
        *(uint2*)(B1l + (S) * B_STG + lrB * RW + wB) = make_uint2(bl0, bl1);    \
        split2(pb3[0], pb3[1], bh0, bl0); split2(pb3[2], pb3[3], bh1, bl1);     \
        *(uint2*)(B3h + (S) * B_STG + lrB * RW + wB) = make_uint2(bh0, bh1);    \
        *(uint2*)(B3l + (S) * B_STG + lrB * RW + wB) = make_uint2(bl0, bl1);    \
    } while (0)

    LOADREG_UP(0);
    STORE_UP(0);
    __syncthreads();

    int stage = 0;
    for (int kb = 0; kb < D_DIM; kb += 16) {
        bool more = (kb + 16) < D_DIM;
        if (more) LOADREG_UP(kb + 16);

        uint32_t aOff = (uint32_t)(stage * A_STG * 4);
        uint32_t bOff = (uint32_t)(stage * B_STG * 4);

        uint32_t ah[4][4], al[4][4];
#pragma unroll
        for (int i = 0; i < 4; i++) {
            ldsm4(ah[i][0], ah[i][1], ah[i][2], ah[i][3], cvAh + aOff + offA[i]);
            ldsm4(al[i][0], al[i][1], al[i][2], al[i][3], cvAl + aOff + offA[i]);
        }
#pragma unroll
        for (int j = 0; j < 2; j++) {
            uint32_t p0, p1, p2, p3;     // b1: hi0, hi1, lo0, lo1
            ldsm4(p0, p1, p2, p3, bB1 + bOff + offB[j]);
            uint32_t q0, q1, q2, q3;     // b3
            ldsm4(q0, q1, q2, q3, bB3 + bOff + offB[j]);
#pragma unroll
            for (int i = 0; i < 4; i++) {
                mma_bf16(c1v[i][j], ah[i][0], ah[i][1], ah[i][2], ah[i][3], p0, p1);
                mma_bf16(c1v[i][j], ah[i][0], ah[i][1], ah[i][2], ah[i][3], p2, p3);
                mma_bf16(c1v[i][j], al[i][0], al[i][1], al[i][2], al[i][3], p0, p1);
                mma_bf16(c3v[i][j], ah[i][0], ah[i][1], ah[i][2], ah[i][3], q0, q1);
                mma_bf16(c3v[i][j], ah[i][0], ah[i][1], ah[i][2], ah[i][3], q2, q3);
                mma_bf16(c3v[i][j], al[i][0], al[i][1], al[i][2], al[i][3], q0, q1);
            }
        }

        if (more) {
            STORE_UP(stage ^ 1);
            __syncthreads();
            stage ^= 1;
        }
    }

    // epilogue: silu(gate) * up * routing_scale -> g_h
#pragma unroll
    for (int i = 0; i < 4; i++) {
#pragma unroll
        for (int j = 0; j < 2; j++) {
            int col = n0 + colBase + j * 8 + 2 * t;
#pragma unroll
            for (int h = 0; h < 2; h++) {
                int rl = rowBase + i * 16 + g + h * 8;
                int p = m0 + rl;
                if (p < end) {
                    float s = scl[rl];
                    float gg0 = c1v[i][j][2 * h + 0], uu0 = c3v[i][j][2 * h + 0];
                    float gg1 = c1v[i][j][2 * h + 1], uu1 = c3v[i][j][2 * h + 1];
                    float* hb = g_h + (size_t)p * F_DIM;
                    hb[col]     = (gg0 / (1.0f + expf(-gg0))) * uu0 * s;
                    hb[col + 1] = (gg1 / (1.0f + expf(-gg1))) * uu1 * s;
                }
            }
        }
    }
}

// ---------------- kernel 5: down projection + scatter-add --------------------
__global__ void __launch_bounds__(256)
down_kernel(const float* __restrict__ w2, float* __restrict__ y) {
    extern __shared__ uint32_t sm[];
    uint32_t* Ah = sm;                    // [2][128][RW]
    uint32_t* Al = Ah + 2 * A_STG;
    uint32_t* Bh = Al + 2 * A_STG;        // [2][64][RW]
    uint32_t* Bl = Bh + 2 * B_STG;
    __shared__ int toks[128];

    int e = blockIdx.z;
    int start = g_offsets[e], end = g_offsets[e + 1];
    int m0 = start + blockIdx.x * 128;
    if (m0 >= end) return;

    int tid = threadIdx.x;
    if (tid < 128) {
        int p = m0 + tid;
        toks[tid] = (p < end) ? g_pair_token[p] : -1;
    }
    __syncthreads();

    int n0 = blockIdx.y * 64;
    int lane = tid & 31, wid = tid >> 5;
    int g = lane >> 2, t = lane & 3;
    int rowBase = (wid & 1) * 64;
    int colBase = (wid >> 1) * 16;

    int lrA = tid >> 1, kaA = (tid & 1) * 8, wA = (tid & 1) * 4;
    int lrB = tid >> 2, kaB = (tid & 3) * 4, wB = (tid & 3) * 2;

    bool rvalid = (m0 + lrA) < end;
    const float* hbp = g_h + (size_t)(rvalid ? (m0 + lrA) : 0) * F_DIM;
    const float* w2b = w2 + ((size_t)e * D_DIM + n0 + lrB) * F_DIM;

    uint32_t cvAh = cvs(Ah), cvAl = cvs(Al);
    uint32_t cvBh = cvs(Bh), cvBl = cvs(Bl);
    int offA[4];
#pragma unroll
    for (int i = 0; i < 4; i++)
        offA[i] = ((rowBase + i * 16 + (lane & 15)) * RW + (lane >> 4) * 4) * 4;
    int offB[2];
#pragma unroll
    for (int j = 0; j < 2; j++)
        offB[j] = ((colBase + j * 8 + (lane & 7)) * RW + ((lane >> 3) & 1) * 4) * 4;
    uint32_t bBB = (lane < 16) ? cvBh : cvBl;

    float cv[4][2][4] = {};

    float pa[8], pb[4];

#define LOADREG_DN(KB) do {                                                     \
        float4 v0 = rvalid ? *(const float4*)(hbp + (KB) + kaA)                 \
                           : make_float4(0.f, 0.f, 0.f, 0.f);                   \
        float4 v1 = rvalid ? *(const float4*)(hbp + (KB) + kaA + 4)             \
                           : make_float4(0.f, 0.f, 0.f, 0.f);                   \
        pa[0]=v0.x; pa[1]=v0.y; pa[2]=v0.z; pa[3]=v0.w;                         \
        pa[4]=v1.x; pa[5]=v1.y; pa[6]=v1.z; pa[7]=v1.w;                         \
        float4 u = *(const float4*)(w2b + (KB) + kaB);                          \
        pb[0]=u.x; pb[1]=u.y; pb[2]=u.z; pb[3]=u.w;                             \
    } while (0)

#define STORE_DN(S) do {                                                        \
        uint32_t h[4], l[4];                                                    \
        split2(pa[0], pa[1], h[0], l[0]); split2(pa[2], pa[3], h[1], l[1]);     \
        split2(pa[4], pa[5], h[2], l[2]); split2(pa[6], pa[7], h[3], l[3]);     \
        *(uint4*)(Ah + (S) * A_STG + lrA * RW + wA) = make_uint4(h[0],h[1],h[2],h[3]); \
        *(uint4*)(Al + (S) * A_STG + lrA * RW + wA) = make_uint4(l[0],l[1],l[2],l[3]); \
        uint32_t bh0, bl0, bh1, bl1;                                            \
        split2(pb[0], pb[1], bh0, bl0); split2(pb[2], pb[3], bh1, bl1);         \
        *(uint2*)(Bh + (S) * B_STG + lrB * RW + wB) = make_uint2(bh0, bh1);     \
        *(uint2*)(Bl + (S) * B_STG + lrB * RW + wB) = make_uint2(bl0, bl1);     \
    } while (0)

    LOADREG_DN(0);
    STORE_DN(0);
    __syncthreads();

    int stage = 0;
    for (int kb = 0; kb < F_DIM; kb += 16) {
        bool more = (kb + 16) < F_DIM;
        if (more) LOADREG_DN(kb + 16);

        uint32_t aOff = (uint32_t)(stage * A_STG * 4);
        uint32_t bOff = (uint32_t)(stage * B_STG * 4);

        uint32_t ah[4][4], al[4][4];
#pragma unroll
        for (int i = 0; i < 4; i++) {
            ldsm4(ah[i][0], ah[i][1], ah[i][2], ah[i][3], cvAh + aOff + offA[i]);
            ldsm4(al[i][0], al[i][1], al[i][2], al[i][3], cvAl + aOff + offA[i]);
        }
#pragma unroll
        for (int j = 0; j < 2; j++) {
            uint32_t p0, p1, p2, p3;     // bh0, bh1, bl0, bl1
            ldsm4(p0, p1, p2, p3, bBB + bOff + offB[j]);
#pragma unroll
            for (int i = 0; i < 4; i++) {
                mma_bf16(cv[i][j], ah[i][0], ah[i][1], ah[i][2], ah[i][3], p0, p1);
                mma_bf16(cv[i][j], ah[i][0], ah[i][1], ah[i][2], ah[i][3], p2, p3);
                mma_bf16(cv[i][j], al[i][0], al[i][1], al[i][2], al[i][3], p0, p1);
            }
        }

        if (more) {
            STORE_DN(stage ^ 1);
            __syncthreads();
            stage ^= 1;
        }
    }

    // epilogue: scatter-add into y
#pragma unroll
    for (int i = 0; i < 4; i++) {
#pragma unroll
        for (int j = 0; j < 2; j++) {
            int col = n0 + colBase + j * 8 + 2 * t;
#pragma unroll
            for (int h = 0; h < 2; h++) {
                int rl = rowBase + i * 16 + g + h * 8;
                if (m0 + rl < end) {
                    int tok = toks[rl];
                    float* yb = y + (size_t)tok * D_DIM;
                    atomicAdd(&yb[col],     cv[i][j][2 * h + 0]);
                    atomicAdd(&yb[col + 1], cv[i][j][2 * h + 1]);
                }
            }
        }
    }
}

// ---------------- launch ------------------------------------------------------
extern "C" void kernel_launch(void* const* d_in, const int* in_sizes, int n_in,
                              void* d_out, int out_size) {
    const float* x  = (const float*)d_in[0];
    const float* gw = (const float*)d_in[1];
    const float* w1 = (const float*)d_in[2];
    const float* w3 = (const float*)d_in[3];
    const float* w2 = (const float*)d_in[4];
    float* y = (float*)d_out;

    // dynamic smem sizes (bytes)
    int smemUp = (2 * A_STG * 2 + 2 * B_STG * 4) * 4;   // 49152 B dynamic (+1KB static)
    int smemDn = (2 * A_STG * 2 + 2 * B_STG * 2) * 4;   // 36864 B dynamic

    // Raise the dynamic-smem cap so static(1KB) + dynamic(48KB) fits.
    // Attribute sets are not stream operations: graph-capture safe, no allocs.
    cudaFuncSetAttribute(ffn_up_kernel, cudaFuncAttributeMaxDynamicSharedMemorySize, 65536);
    cudaFuncSetAttribute(down_kernel,   cudaFuncAttributeMaxDynamicSharedMemorySize, 65536);

    zero_kernel<<<4096, 256>>>(y, (size_t)T_TOK * D_DIM);
    routing_kernel<<<T_TOK / 8, 256>>>(x, gw);
    scan_kernel<<<1, 32>>>();
    fill_kernel<<<T_TOK / 256, 256>>>();

    dim3 gA(P_MAX / 128, F_DIM / 64, E_NUM);
    ffn_up_kernel<<<gA, 256, smemUp>>>(x, w1, w3);

    dim3 gB(P_MAX / 128, D_DIM / 64, E_NUM);
    down_kernel<<<gB, 256, smemDn>>>(w2, y);
}

// round 13
// speedup vs baseline: 3.8205x; 1.9897x over previous
#include <cuda_runtime.h>
#include <cuda_fp16.h>
#include <math.h>
#include <stdint.h>

// Problem constants (fixed shapes from reference)
#define T_TOK 8192      // B*S tokens
#define D_DIM 2048
#define E_NUM 8
#define F_DIM 2048
#define P_MAX (T_TOK * 2)   // token-expert pairs (top-2)

// ---------------- device scratch (static; no allocations allowed) ------------
__device__ float g_h[(size_t)P_MAX * F_DIM];   // scaled hidden
__device__ int   g_pair_token[P_MAX];
__device__ float g_pair_scale[P_MAX];
__device__ int   g_counts[E_NUM];
__device__ int   g_offsets[E_NUM + 1];
__device__ int   g_cursor[E_NUM];
__device__ int   g_tok_e[T_TOK * 2];
__device__ float g_tok_w[T_TOK * 2];

// ---------------- helpers -----------------------------------------------------
__device__ __forceinline__ void mma_f16(float* c,
                                        uint32_t a0, uint32_t a1, uint32_t a2, uint32_t a3,
                                        uint32_t b0, uint32_t b1) {
    asm volatile(
        "mma.sync.aligned.m16n8k16.row.col.f32.f16.f16.f32 "
        "{%0,%1,%2,%3}, {%4,%5,%6,%7}, {%8,%9}, {%0,%1,%2,%3};"
        : "+f"(c[0]), "+f"(c[1]), "+f"(c[2]), "+f"(c[3])
        : "r"(a0), "r"(a1), "r"(a2), "r"(a3), "r"(b0), "r"(b1));
}

__device__ __forceinline__ void ldsm4(uint32_t& d0, uint32_t& d1, uint32_t& d2, uint32_t& d3,
                                      uint32_t addr) {
    asm volatile("ldmatrix.sync.aligned.m8n8.x4.shared.b16 {%0,%1,%2,%3}, [%4];"
                 : "=r"(d0), "=r"(d1), "=r"(d2), "=r"(d3) : "r"(addr));
}

__device__ __forceinline__ uint32_t cvt2(float x0, float x1) {
    __half2 h = __float22half2_rn(make_float2(x0, x1));
    return *(uint32_t*)&h;
}

__device__ __forceinline__ uint32_t cvs(const void* p) {
    return (uint32_t)__cvta_generic_to_shared(p);
}

// smem geometry: rows of 8 fp16x2 words (k16), padded stride 12 words.
// LDSM 8-row phases: banks [12r mod 32, +4) = all 32 banks exactly once.
#define RW 12
#define A_STG (128 * RW)   // words per A stage
#define B_STG (64 * RW)    // words per B stage

// ---------------- kernel 0: zero output + counters ---------------------------
__global__ void zero_kernel(float* __restrict__ y, size_t n) {
    size_t i = (size_t)blockIdx.x * blockDim.x + threadIdx.x;
    size_t stride = (size_t)gridDim.x * blockDim.x;
    for (; i < n; i += stride) y[i] = 0.0f;
    if (blockIdx.x == 0 && threadIdx.x < E_NUM) g_counts[threadIdx.x] = 0;
}

// ---------------- kernel 1: routing (one warp per token, fp32) ---------------
__global__ void routing_kernel(const float* __restrict__ x,
                               const float* __restrict__ gw) {
    int gwarp = (int)((blockIdx.x * blockDim.x + threadIdx.x) >> 5);
    int lane = threadIdx.x & 31;
    if (gwarp >= T_TOK) return;
    const float* xr = x + (size_t)gwarp * D_DIM;

    float acc[E_NUM];
#pragma unroll
    for (int e = 0; e < E_NUM; e++) acc[e] = 0.0f;

    for (int d = lane * 4; d < D_DIM; d += 32 * 4) {
        float4 xv = *(const float4*)(xr + d);
#pragma unroll
        for (int e = 0; e < E_NUM; e++) {
            float4 gv = *(const float4*)(gw + e * D_DIM + d);
            acc[e] += xv.x * gv.x + xv.y * gv.y + xv.z * gv.z + xv.w * gv.w;
        }
    }
#pragma unroll
    for (int e = 0; e < E_NUM; e++) {
#pragma unroll
        for (int o = 16; o; o >>= 1)
            acc[e] += __shfl_xor_sync(0xffffffffu, acc[e], o);
    }
    if (lane == 0) {
        float m = acc[0];
#pragma unroll
        for (int e = 1; e < E_NUM; e++) m = fmaxf(m, acc[e]);
        float p[E_NUM];
        float s = 0.0f;
#pragma unroll
        for (int e = 0; e < E_NUM; e++) { p[e] = expf(acc[e] - m); s += p[e]; }
        float inv = 1.0f / s;
        int b0 = 0; float v0 = p[0];
#pragma unroll
        for (int e = 1; e < E_NUM; e++) if (p[e] > v0) { v0 = p[e]; b0 = e; }
        int b1 = -1; float v1 = -1.0f;
#pragma unroll
        for (int e = 0; e < E_NUM; e++)
            if (e != b0 && p[e] > v1) { v1 = p[e]; b1 = e; }

        g_tok_e[2 * gwarp]     = b0;  g_tok_w[2 * gwarp]     = v0 * inv;
        g_tok_e[2 * gwarp + 1] = b1;  g_tok_w[2 * gwarp + 1] = v1 * inv;
        atomicAdd(&g_counts[b0], 1);
        atomicAdd(&g_counts[b1], 1);
    }
}

// ---------------- kernel 2: exclusive scan of expert counts ------------------
__global__ void scan_kernel() {
    if (threadIdx.x == 0) {
        int s = 0;
        for (int e = 0; e < E_NUM; e++) {
            g_offsets[e] = s;
            g_cursor[e] = s;
            s += g_counts[e];
        }
        g_offsets[E_NUM] = s;
    }
}

// ---------------- kernel 3: fill per-expert pair lists -----------------------
__global__ void fill_kernel() {
    int t = blockIdx.x * blockDim.x + threadIdx.x;
    if (t >= T_TOK) return;
#pragma unroll
    for (int k = 0; k < 2; k++) {
        int e = g_tok_e[2 * t + k];
        int p = atomicAdd(&g_cursor[e], 1);
        g_pair_token[p] = t;
        g_pair_scale[p] = g_tok_w[2 * t + k];
    }
}

// ---------------- kernel 4: gate/up GEMMs + SiLU + scale (fp16 mma) ----------
// Block 128(M) x 64(N), 8 warps 2x4, warp tile 64x16, K16 double-buffered.
__global__ void __launch_bounds__(256)
ffn_up_kernel(const float* __restrict__ x,
              const float* __restrict__ w1,
              const float* __restrict__ w3) {
    extern __shared__ uint32_t sm[];
    uint32_t* As  = sm;                   // [2][128][RW]
    uint32_t* B1s = As + 2 * A_STG;       // [2][64][RW]
    uint32_t* B3s = B1s + 2 * B_STG;
    __shared__ int   toks[128];
    __shared__ float scl[128];

    int e = blockIdx.z;
    int start = g_offsets[e], end = g_offsets[e + 1];
    int m0 = start + blockIdx.x * 128;
    if (m0 >= end) return;

    int tid = threadIdx.x;
    if (tid < 128) {
        int p = m0 + tid;
        toks[tid] = (p < end) ? g_pair_token[p] : -1;
        scl[tid]  = (p < end) ? g_pair_scale[p] : 0.0f;
    }
    __syncthreads();

    int n0 = blockIdx.y * 64;
    int lane = tid & 31, wid = tid >> 5;
    int g = lane >> 2, t = lane & 3;
    int rowBase = (wid & 1) * 64;
    int colBase = (wid >> 1) * 16;

    // loaders: A 128 rows x 16 floats (2 thr/row, 8 floats), B 64 rows (4 thr/row, 4 floats)
    int lrA = tid >> 1, kaA = (tid & 1) * 8, wA = (tid & 1) * 4;
    int lrB = tid >> 2, kaB = (tid & 3) * 4, wB = (tid & 3) * 2;

    int tokA = toks[lrA];
    const float* xb  = (tokA >= 0) ? (x + (size_t)tokA * D_DIM) : x;
    const float* w1b = w1 + ((size_t)e * F_DIM + n0 + lrB) * D_DIM;
    const float* w3b = w3 + ((size_t)e * F_DIM + n0 + lrB) * D_DIM;

    // ldmatrix addresses
    uint32_t cvA = cvs(As), cvB1 = cvs(B1s), cvB3 = cvs(B3s);
    int offA[4];
#pragma unroll
    for (int i = 0; i < 4; i++)
        offA[i] = ((rowBase + i * 16 + (lane & 15)) * RW + (lane >> 4) * 4) * 4;
    // one x4 covers both n-groups: m0,m1 = j0 (k lo/hi), m2,m3 = j1
    int offB = ((colBase + ((lane >> 4) & 1) * 8 + (lane & 7)) * RW
                + ((lane >> 3) & 1) * 4) * 4;

    float c1v[4][2][4] = {};
    float c3v[4][2][4] = {};

    float pa[8], pb1[4], pb3[4];

#define LOADREG_UP(KB) do {                                                     \
        float4 v0 = (tokA >= 0) ? *(const float4*)(xb + (KB) + kaA)             \
                                : make_float4(0.f, 0.f, 0.f, 0.f);              \
        float4 v1 = (tokA >= 0) ? *(const float4*)(xb + (KB) + kaA + 4)         \
                                : make_float4(0.f, 0.f, 0.f, 0.f);              \
        pa[0]=v0.x; pa[1]=v0.y; pa[2]=v0.z; pa[3]=v0.w;                         \
        pa[4]=v1.x; pa[5]=v1.y; pa[6]=v1.z; pa[7]=v1.w;                         \
        float4 u1 = *(const float4*)(w1b + (KB) + kaB);                         \
        float4 u3 = *(const float4*)(w3b + (KB) + kaB);                         \
        pb1[0]=u1.x; pb1[1]=u1.y; pb1[2]=u1.z; pb1[3]=u1.w;                     \
        pb3[0]=u3.x; pb3[1]=u3.y; pb3[2]=u3.z; pb3[3]=u3.w;                     \
    } while (0)

#define STORE_UP(S) do {                                                        \
        *(uint4*)(As + (S) * A_STG + lrA * RW + wA) =                           \
            make_uint4(cvt2(pa[0], pa[1]), cvt2(pa[2], pa[3]),                  \
                       cvt2(pa[4], pa[5]), cvt2(pa[6], pa[7]));                 \
        *(uint2*)(B1s + (S) * B_STG + lrB * RW + wB) =                          \
            make_uint2(cvt2(pb1[0], pb1[1]), cvt2(pb1[2], pb1[3]));             \
        *(uint2*)(B3s + (S) * B_STG + lrB * RW + wB) =                          \
            make_uint2(cvt2(pb3[0], pb3[1]), cvt2(pb3[2], pb3[3]));             \
    } while (0)

    LOADREG_UP(0);
    STORE_UP(0);
    __syncthreads();

    int stage = 0;
    for (int kb = 0; kb < D_DIM; kb += 16) {
        bool more = (kb + 16) < D_DIM;
        if (more) LOADREG_UP(kb + 16);

        uint32_t aOff = (uint32_t)(stage * A_STG * 4);
        uint32_t bOff = (uint32_t)(stage * B_STG * 4);

        uint32_t a[4][4];
#pragma unroll
        for (int i = 0; i < 4; i++)
            ldsm4(a[i][0], a[i][1], a[i][2], a[i][3], cvA + aOff + offA[i]);
        uint32_t p[4], q[4];
        ldsm4(p[0], p[1], p[2], p[3], cvB1 + bOff + offB);
        ldsm4(q[0], q[1], q[2], q[3], cvB3 + bOff + offB);

#pragma unroll
        for (int j = 0; j < 2; j++) {
#pragma unroll
            for (int i = 0; i < 4; i++) {
                mma_f16(c1v[i][j], a[i][0], a[i][1], a[i][2], a[i][3], p[2*j], p[2*j+1]);
                mma_f16(c3v[i][j], a[i][0], a[i][1], a[i][2], a[i][3], q[2*j], q[2*j+1]);
            }
        }

        if (more) {
            STORE_UP(stage ^ 1);
            __syncthreads();
            stage ^= 1;
        }
    }

    // epilogue: silu(gate) * up * routing_scale -> g_h
#pragma unroll
    for (int i = 0; i < 4; i++) {
#pragma unroll
        for (int j = 0; j < 2; j++) {
            int col = n0 + colBase + j * 8 + 2 * t;
#pragma unroll
            for (int h = 0; h < 2; h++) {
                int rl = rowBase + i * 16 + g + h * 8;
                int p2 = m0 + rl;
                if (p2 < end) {
                    float s = scl[rl];
                    float gg0 = c1v[i][j][2 * h + 0], uu0 = c3v[i][j][2 * h + 0];
                    float gg1 = c1v[i][j][2 * h + 1], uu1 = c3v[i][j][2 * h + 1];
                    float* hb = g_h + (size_t)p2 * F_DIM;
                    hb[col]     = (gg0 / (1.0f + expf(-gg0))) * uu0 * s;
                    hb[col + 1] = (gg1 / (1.0f + expf(-gg1))) * uu1 * s;
                }
            }
        }
    }
}

// ---------------- kernel 5: down projection + scatter-add (fp16 mma) ---------
__global__ void __launch_bounds__(256)
down_kernel(const float* __restrict__ w2, float* __restrict__ y) {
    extern __shared__ uint32_t sm[];
    uint32_t* As = sm;                    // [2][128][RW]
    uint32_t* Bs = As + 2 * A_STG;        // [2][64][RW]
    __shared__ int toks[128];

    int e = blockIdx.z;
    int start = g_offsets[e], end = g_offsets[e + 1];
    int m0 = start + blockIdx.x * 128;
    if (m0 >= end) return;

    int tid = threadIdx.x;
    if (tid < 128) {
        int p = m0 + tid;
        toks[tid] = (p < end) ? g_pair_token[p] : -1;
    }
    __syncthreads();

    int n0 = blockIdx.y * 64;
    int lane = tid & 31, wid = tid >> 5;
    int g = lane >> 2, t = lane & 3;
    int rowBase = (wid & 1) * 64;
    int colBase = (wid >> 1) * 16;

    int lrA = tid >> 1, kaA = (tid & 1) * 8, wA = (tid & 1) * 4;
    int lrB = tid >> 2, kaB = (tid & 3) * 4, wB = (tid & 3) * 2;

    bool rvalid = (m0 + lrA) < end;
    const float* hbp = g_h + (size_t)(rvalid ? (m0 + lrA) : 0) * F_DIM;
    const float* w2b = w2 + ((size_t)e * D_DIM + n0 + lrB) * F_DIM;

    uint32_t cvA = cvs(As), cvB = cvs(Bs);
    int offA[4];
#pragma unroll
    for (int i = 0; i < 4; i++)
        offA[i] = ((rowBase + i * 16 + (lane & 15)) * RW + (lane >> 4) * 4) * 4;
    int offB = ((colBase + ((lane >> 4) & 1) * 8 + (lane & 7)) * RW
                + ((lane >> 3) & 1) * 4) * 4;

    float cv[4][2][4] = {};

    float pa[8], pb[4];

#define LOADREG_DN(KB) do {                                                     \
        float4 v0 = rvalid ? *(const float4*)(hbp + (KB) + kaA)                 \
                           : make_float4(0.f, 0.f, 0.f, 0.f);                   \
        float4 v1 = rvalid ? *(const float4*)(hbp + (KB) + kaA + 4)             \
                           : make_float4(0.f, 0.f, 0.f, 0.f);                   \
        pa[0]=v0.x; pa[1]=v0.y; pa[2]=v0.z; pa[3]=v0.w;                         \
        pa[4]=v1.x; pa[5]=v1.y; pa[6]=v1.z; pa[7]=v1.w;                         \
        float4 u = *(const float4*)(w2b + (KB) + kaB);                          \
        pb[0]=u.x; pb[1]=u.y; pb[2]=u.z; pb[3]=u.w;                             \
    } while (0)

#define STORE_DN(S) do {                                                        \
        *(uint4*)(As + (S) * A_STG + lrA * RW + wA) =                           \
            make_uint4(cvt2(pa[0], pa[1]), cvt2(pa[2], pa[3]),                  \
                       cvt2(pa[4], pa[5]), cvt2(pa[6], pa[7]));                 \
        *(uint2*)(Bs + (S) * B_STG + lrB * RW + wB) =                           \
            make_uint2(cvt2(pb[0], pb[1]), cvt2(pb[2], pb[3]));                 \
    } while (0)

    LOADREG_DN(0);
    STORE_DN(0);
    __syncthreads();

    int stage = 0;
    for (int kb = 0; kb < F_DIM; kb += 16) {
        bool more = (kb + 16) < F_DIM;
        if (more) LOADREG_DN(kb + 16);

        uint32_t aOff = (uint32_t)(stage * A_STG * 4);
        uint32_t bOff = (uint32_t)(stage * B_STG * 4);

        uint32_t a[4][4];
#pragma unroll
        for (int i = 0; i < 4; i++)
            ldsm4(a[i][0], a[i][1], a[i][2], a[i][3], cvA + aOff + offA[i]);
        uint32_t p[4];
        ldsm4(p[0], p[1], p[2], p[3], cvB + bOff + offB);

#pragma unroll
        for (int j = 0; j < 2; j++)
#pragma unroll
            for (int i = 0; i < 4; i++)
                mma_f16(cv[i][j], a[i][0], a[i][1], a[i][2], a[i][3], p[2*j], p[2*j+1]);

        if (more) {
            STORE_DN(stage ^ 1);
            __syncthreads();
            stage ^= 1;
        }
    }

    // epilogue: scatter-add into y
#pragma unroll
    for (int i = 0; i < 4; i++) {
#pragma unroll
        for (int j = 0; j < 2; j++) {
            int col = n0 + colBase + j * 8 + 2 * t;
#pragma unroll
            for (int h = 0; h < 2; h++) {
                int rl = rowBase + i * 16 + g + h * 8;
                if (m0 + rl < end) {
                    int tok = toks[rl];
                    float* yb = y + (size_t)tok * D_DIM;
                    atomicAdd(&yb[col],     cv[i][j][2 * h + 0]);
                    atomicAdd(&yb[col + 1], cv[i][j][2 * h + 1]);
                }
            }
        }
    }
}

// ---------------- launch ------------------------------------------------------
extern "C" void kernel_launch(void* const* d_in, const int* in_sizes, int n_in,
                              void* d_out, int out_size) {
    const float* x  = (const float*)d_in[0];
    const float* gw = (const float*)d_in[1];
    const float* w1 = (const float*)d_in[2];
    const float* w3 = (const float*)d_in[3];
    const float* w2 = (const float*)d_in[4];
    float* y = (float*)d_out;

    // dynamic smem (bytes): up 24576, down 18432 — well under limits
    int smemUp = (2 * A_STG + 2 * B_STG * 2) * 4;
    int smemDn = (2 * A_STG + 2 * B_STG) * 4;

    cudaFuncSetAttribute(ffn_up_kernel, cudaFuncAttributeMaxDynamicSharedMemorySize, 65536);
    cudaFuncSetAttribute(down_kernel,   cudaFuncAttributeMaxDynamicSharedMemorySize, 65536);

    zero_kernel<<<4096, 256>>>(y, (size_t)T_TOK * D_DIM);
    routing_kernel<<<T_TOK / 8, 256>>>(x, gw);
    scan_kernel<<<1, 32>>>();
    fill_kernel<<<T_TOK / 256, 256>>>();

    dim3 gA(P_MAX / 128, F_DIM / 64, E_NUM);
    ffn_up_kernel<<<gA, 256, smemUp>>>(x, w1, w3);

    dim3 gB(P_MAX / 128, D_DIM / 64, E_NUM);
    down_kernel<<<gB, 256, smemDn>>>(w2, y);
}

// round 15
// speedup vs baseline: 4.1618x; 1.0894x over previous
#include <cuda_runtime.h>
#include <cuda_fp16.h>
#include <math.h>
#include <stdint.h>

// Problem constants (fixed shapes from reference)
#define T_TOK 8192      // B*S tokens
#define D_DIM 2048
#define E_NUM 8
#define F_DIM 2048
#define P_MAX (T_TOK * 2)   // token-expert pairs (top-2)

// ---------------- device scratch (static; no allocations allowed) ------------
__device__ __half g_xh[(size_t)T_TOK * D_DIM];          // x in fp16
__device__ __half g_w1h[(size_t)E_NUM * F_DIM * D_DIM]; // w1 in fp16
__device__ __half g_w3h[(size_t)E_NUM * F_DIM * D_DIM]; // w3 in fp16
__device__ __half g_w2h[(size_t)E_NUM * D_DIM * F_DIM]; // w2 in fp16
__device__ __half g_hh[(size_t)P_MAX * F_DIM];          // scaled hidden, fp16
__device__ int   g_pair_token[P_MAX];
__device__ float g_pair_scale[P_MAX];
__device__ int   g_counts[E_NUM];
__device__ int   g_offsets[E_NUM + 1];
__device__ int   g_cursor[E_NUM];
__device__ int   g_tok_e[T_TOK * 2];
__device__ float g_tok_w[T_TOK * 2];

// ---------------- helpers -----------------------------------------------------
__device__ __forceinline__ void mma_f16(float* c,
                                        uint32_t a0, uint32_t a1, uint32_t a2, uint32_t a3,
                                        uint32_t b0, uint32_t b1) {
    asm volatile(
        "mma.sync.aligned.m16n8k16.row.col.f32.f16.f16.f32 "
        "{%0,%1,%2,%3}, {%4,%5,%6,%7}, {%8,%9}, {%0,%1,%2,%3};"
        : "+f"(c[0]), "+f"(c[1]), "+f"(c[2]), "+f"(c[3])
        : "r"(a0), "r"(a1), "r"(a2), "r"(a3), "r"(b0), "r"(b1));
}

__device__ __forceinline__ void ldsm4(uint32_t& d0, uint32_t& d1, uint32_t& d2, uint32_t& d3,
                                      uint32_t addr) {
    asm volatile("ldmatrix.sync.aligned.m8n8.x4.shared.b16 {%0,%1,%2,%3}, [%4];"
                 : "=r"(d0), "=r"(d1), "=r"(d2), "=r"(d3) : "r"(addr));
}

__device__ __forceinline__ uint32_t cvs(const void* p) {
    return (uint32_t)__cvta_generic_to_shared(p);
}

// smem geometry: rows of 8 fp16x2 words (k16), padded stride 12 words.
// LDSM 8-row phases: banks [12r mod 32, +4) = all 32 banks exactly once.
#define RW 12
#define A_STG (128 * RW)   // words per 128-row stage (A and B both 128 rows now)

// ---------------- kernel 0: zero output + counters ---------------------------
__global__ void zero_kernel(float* __restrict__ y, size_t n) {
    size_t i = (size_t)blockIdx.x * blockDim.x + threadIdx.x;
    size_t stride = (size_t)gridDim.x * blockDim.x;
    for (; i < n; i += stride) y[i] = 0.0f;
    if (blockIdx.x == 0 && threadIdx.x < E_NUM) g_counts[threadIdx.x] = 0;
}

// ---------------- kernel 0b: fp32 -> fp16 conversion --------------------------
__global__ void convert_kernel(const float* __restrict__ src, __half* __restrict__ dst,
                               size_t n4) {
    size_t i = (size_t)blockIdx.x * blockDim.x + threadIdx.x;
    size_t stride = (size_t)gridDim.x * blockDim.x;
    for (; i < n4; i += stride) {
        float4 v = *(const float4*)(src + i * 4);
        __half2 h0 = __floats2half2_rn(v.x, v.y);
        __half2 h1 = __floats2half2_rn(v.z, v.w);
        *(uint2*)(dst + i * 4) = make_uint2(*(uint32_t*)&h0, *(uint32_t*)&h1);
    }
}

// ---------------- kernel 1: routing (one warp per token, fp32) ---------------
__global__ void routing_kernel(const float* __restrict__ x,
                               const float* __restrict__ gw) {
    int gwarp = (int)((blockIdx.x * blockDim.x + threadIdx.x) >> 5);
    int lane = threadIdx.x & 31;
    if (gwarp >= T_TOK) return;
    const float* xr = x + (size_t)gwarp * D_DIM;

    float acc[E_NUM];
#pragma unroll
    for (int e = 0; e < E_NUM; e++) acc[e] = 0.0f;

    for (int d = lane * 4; d < D_DIM; d += 32 * 4) {
        float4 xv = *(const float4*)(xr + d);
#pragma unroll
        for (int e = 0; e < E_NUM; e++) {
            float4 gv = *(const float4*)(gw + e * D_DIM + d);
            acc[e] += xv.x * gv.x + xv.y * gv.y + xv.z * gv.z + xv.w * gv.w;
        }
    }
#pragma unroll
    for (int e = 0; e < E_NUM; e++) {
#pragma unroll
        for (int o = 16; o; o >>= 1)
            acc[e] += __shfl_xor_sync(0xffffffffu, acc[e], o);
    }
    if (lane == 0) {
        float m = acc[0];
#pragma unroll
        for (int e = 1; e < E_NUM; e++) m = fmaxf(m, acc[e]);
        float p[E_NUM];
        float s = 0.0f;
#pragma unroll
        for (int e = 0; e < E_NUM; e++) { p[e] = expf(acc[e] - m); s += p[e]; }
        float inv = 1.0f / s;
        int b0 = 0; float v0 = p[0];
#pragma unroll
        for (int e = 1; e < E_NUM; e++) if (p[e] > v0) { v0 = p[e]; b0 = e; }
        int b1 = -1; float v1 = -1.0f;
#pragma unroll
        for (int e = 0; e < E_NUM; e++)
            if (e != b0 && p[e] > v1) { v1 = p[e]; b1 = e; }

        g_tok_e[2 * gwarp]     = b0;  g_tok_w[2 * gwarp]     = v0 * inv;
        g_tok_e[2 * gwarp + 1] = b1;  g_tok_w[2 * gwarp + 1] = v1 * inv;
        atomicAdd(&g_counts[b0], 1);
        atomicAdd(&g_counts[b1], 1);
    }
}

// ---------------- kernel 2: exclusive scan of expert counts ------------------
__global__ void scan_kernel() {
    if (threadIdx.x == 0) {
        int s = 0;
        for (int e = 0; e < E_NUM; e++) {
            g_offsets[e] = s;
            g_cursor[e] = s;
            s += g_counts[e];
        }
        g_offsets[E_NUM] = s;
    }
}

// ---------------- kernel 3: fill per-expert pair lists -----------------------
__global__ void fill_kernel() {
    int t = blockIdx.x * blockDim.x + threadIdx.x;
    if (t >= T_TOK) return;
#pragma unroll
    for (int k = 0; k < 2; k++) {
        int e = g_tok_e[2 * t + k];
        int p = atomicAdd(&g_cursor[e], 1);
        g_pair_token[p] = t;
        g_pair_scale[p] = g_tok_w[2 * t + k];
    }
}

// ---------------- kernel 4: gate/up GEMMs + SiLU + scale (fp16 mma) ----------
// Block 128(M) x 128(N), 512 threads (16 warps 2x8), warp tile 64x16.
// K16 double-buffered; inputs pre-converted fp16.
__global__ void __launch_bounds__(512)
ffn_up_kernel() {
    extern __shared__ uint32_t sm[];
    uint32_t* As  = sm;                   // [2][128][RW]
    uint32_t* B1s = As + 2 * A_STG;       // [2][128][RW]
    uint32_t* B3s = B1s + 2 * A_STG;
    __shared__ int   toks[128];
    __shared__ float scl[128];

    int e = blockIdx.z;
    int start = g_offsets[e], end = g_offsets[e + 1];
    int m0 = start + blockIdx.x * 128;
    if (m0 >= end) return;

    int tid = threadIdx.x;
    if (tid < 128) {
        int p = m0 + tid;
        toks[tid] = (p < end) ? g_pair_token[p] : -1;
        scl[tid]  = (p < end) ? g_pair_scale[p] : 0.0f;
    }
    __syncthreads();

    int n0 = blockIdx.y * 128;
    int lane = tid & 31, wid = tid >> 5;
    int g = lane >> 2, t = lane & 3;
    int rowBase = (wid & 1) * 64;     // 2 row groups of 64
    int colBase = (wid >> 1) * 16;    // 8 col groups of 16

    // loaders: 128 rows x 8 words each for A/B1/B3; 4 thr/row x uint2
    int lr = tid >> 2, ka = (tid & 3) * 4, wS = (tid & 3) * 2;

    int tokA = toks[lr];
    const __half* xb  = g_xh + (size_t)(tokA >= 0 ? tokA : 0) * D_DIM + ka;
    const __half* w1b = g_w1h + ((size_t)e * F_DIM + n0 + lr) * D_DIM + ka;
    const __half* w3b = g_w3h + ((size_t)e * F_DIM + n0 + lr) * D_DIM + ka;

    uint32_t cvA = cvs(As), cvB1 = cvs(B1s), cvB3 = cvs(B3s);
    int offA[4];
#pragma unroll
    for (int i = 0; i < 4; i++)
        offA[i] = ((rowBase + i * 16 + (lane & 15)) * RW + (lane >> 4) * 4) * 4;
    int offB = ((colBase + ((lane >> 4) & 1) * 8 + (lane & 7)) * RW
                + ((lane >> 3) & 1) * 4) * 4;

    float c1v[4][2][4] = {};
    float c3v[4][2][4] = {};

    uint2 qa, qb1, qb3;
    const uint2 zz = make_uint2(0u, 0u);

#define LOADREG_UP(KB) do {                                                     \
        qa  = (tokA >= 0) ? *(const uint2*)(xb + (KB)) : zz;                    \
        qb1 = *(const uint2*)(w1b + (KB));                                      \
        qb3 = *(const uint2*)(w3b + (KB));                                      \
    } while (0)

#define STORE_UP(S) do {                                                        \
        *(uint2*)(As  + (S) * A_STG + lr * RW + wS) = qa;                       \
        *(uint2*)(B1s + (S) * A_STG + lr * RW + wS) = qb1;                      \
        *(uint2*)(B3s + (S) * A_STG + lr * RW + wS) = qb3;                      \
    } while (0)

    LOADREG_UP(0);
    STORE_UP(0);
    __syncthreads();

    int stage = 0;
    for (int kb = 0; kb < D_DIM; kb += 16) {
        bool more = (kb + 16) < D_DIM;
        if (more) LOADREG_UP(kb + 16);

        uint32_t aOff = (uint32_t)(stage * A_STG * 4);

        uint32_t a[4][4];
#pragma unroll
        for (int i = 0; i < 4; i++)
            ldsm4(a[i][0], a[i][1], a[i][2], a[i][3], cvA + aOff + offA[i]);
        uint32_t p[4], q[4];
        ldsm4(p[0], p[1], p[2], p[3], cvB1 + aOff + offB);
        ldsm4(q[0], q[1], q[2], q[3], cvB3 + aOff + offB);

#pragma unroll
        for (int j = 0; j < 2; j++) {
#pragma unroll
            for (int i = 0; i < 4; i++) {
                mma_f16(c1v[i][j], a[i][0], a[i][1], a[i][2], a[i][3], p[2*j], p[2*j+1]);
                mma_f16(c3v[i][j], a[i][0], a[i][1], a[i][2], a[i][3], q[2*j], q[2*j+1]);
            }
        }

        if (more) {
            STORE_UP(stage ^ 1);
            __syncthreads();
            stage ^= 1;
        }
    }

    // epilogue: silu(gate) * up * routing_scale -> g_hh (fp16)
#pragma unroll
    for (int i = 0; i < 4; i++) {
#pragma unroll
        for (int j = 0; j < 2; j++) {
            int col = n0 + colBase + j * 8 + 2 * t;
#pragma unroll
            for (int h = 0; h < 2; h++) {
                int rl = rowBase + i * 16 + g + h * 8;
                int p2 = m0 + rl;
                if (p2 < end) {
                    float s = scl[rl];
                    float gg0 = c1v[i][j][2 * h + 0], uu0 = c3v[i][j][2 * h + 0];
                    float gg1 = c1v[i][j][2 * h + 1], uu1 = c3v[i][j][2 * h + 1];
                    float r0 = (gg0 / (1.0f + expf(-gg0))) * uu0 * s;
                    float r1 = (gg1 / (1.0f + expf(-gg1))) * uu1 * s;
                    __half2 hv = __floats2half2_rn(r0, r1);
                    *(uint32_t*)(g_hh + (size_t)p2 * F_DIM + col) = *(uint32_t*)&hv;
                }
            }
        }
    }
}

// ---------------- kernel 5: down projection + scatter-add (fp16 mma) ---------
// Block 128(M) x 128(N over D), 512 threads.
__global__ void __launch_bounds__(512)
down_kernel(float* __restrict__ y) {
    extern __shared__ uint32_t sm[];
    uint32_t* As = sm;                    // [2][128][RW]
    uint32_t* Bs = As + 2 * A_STG;        // [2][128][RW]
    __shared__ int toks[128];

    int e = blockIdx.z;
    int start = g_offsets[e], end = g_offsets[e + 1];
    int m0 = start + blockIdx.x * 128;
    if (m0 >= end) return;

    int tid = threadIdx.x;
    if (tid < 128) {
        int p = m0 + tid;
        toks[tid] = (p < end) ? g_pair_token[p] : -1;
    }
    __syncthreads();

    int n0 = blockIdx.y * 128;
    int lane = tid & 31, wid = tid >> 5;
    int g = lane >> 2, t = lane & 3;
    int rowBase = (wid & 1) * 64;
    int colBase = (wid >> 1) * 16;

    int lr = tid >> 2, ka = (tid & 3) * 4, wS = (tid & 3) * 2;

    bool rvalid = (m0 + lr) < end;
    const __half* hbp = g_hh + (size_t)(rvalid ? (m0 + lr) : 0) * F_DIM + ka;
    const __half* w2b = g_w2h + ((size_t)e * D_DIM + n0 + lr) * F_DIM + ka;

    uint32_t cvA = cvs(As), cvB = cvs(Bs);
    int offA[4];
#pragma unroll
    for (int i = 0; i < 4; i++)
        offA[i] = ((rowBase + i * 16 + (lane & 15)) * RW + (lane >> 4) * 4) * 4;
    int offB = ((colBase + ((lane >> 4) & 1) * 8 + (lane & 7)) * RW
                + ((lane >> 3) & 1) * 4) * 4;

    float cv[4][2][4] = {};

    uint2 qa, qb;
    const uint2 zz = make_uint2(0u, 0u);

#define LOADREG_DN(KB) do {                                                     \
        qa = rvalid ? *(const uint2*)(hbp + (KB)) : zz;                         \
        qb = *(const uint2*)(w2b + (KB));                                       \
    } while (0)

#define STORE_DN(S) do {                                                        \
        *(uint2*)(As + (S) * A_STG + lr * RW + wS) = qa;                        \
        *(uint2*)(Bs + (S) * A_STG + lr * RW + wS) = qb;                        \
    } while (0)

    LOADREG_DN(0);
    STORE_DN(0);
    __syncthreads();

    int stage = 0;
    for (int kb = 0; kb < F_DIM; kb += 16) {
        bool more = (kb + 16) < F_DIM;
        if (more) LOADREG_DN(kb + 16);

        uint32_t aOff = (uint32_t)(stage * A_STG * 4);

        uint32_t a[4][4];
#pragma unroll
        for (int i = 0; i < 4; i++)
            ldsm4(a[i][0], a[i][1], a[i][2], a[i][3], cvA + aOff + offA[i]);
        uint32_t p[4];
        ldsm4(p[0], p[1], p[2], p[3], cvB + aOff + offB);

#pragma unroll
        for (int j = 0; j < 2; j++)
#pragma unroll
            for (int i = 0; i < 4; i++)
                mma_f16(cv[i][j], a[i][0], a[i][1], a[i][2], a[i][3], p[2*j], p[2*j+1]);

        if (more) {
            STORE_DN(stage ^ 1);
            __syncthreads();
            stage ^= 1;
        }
    }

    // epilogue: scatter-add into y (fp32)
#pragma unroll
    for (int i = 0; i < 4; i++) {
#pragma unroll
        for (int j = 0; j < 2; j++) {
            int col = n0 + colBase + j * 8 + 2 * t;
#pragma unroll
            for (int h = 0; h < 2; h++) {
                int rl = rowBase + i * 16 + g + h * 8;
                if (m0 + rl < end) {
                    int tok = toks[rl];
                    float* yb = y + (size_t)tok * D_DIM;
                    atomicAdd(&yb[col],     cv[i][j][2 * h + 0]);
                    atomicAdd(&yb[col + 1], cv[i][j][2 * h + 1]);
                }
            }
        }
    }
}

// ---------------- launch ------------------------------------------------------
extern "C" void kernel_launch(void* const* d_in, const int* in_sizes, int n_in,
                              void* d_out, int out_size) {
    const float* x  = (const float*)d_in[0];
    const float* gw = (const float*)d_in[1];
    const float* w1 = (const float*)d_in[2];
    const float* w3 = (const float*)d_in[3];
    const float* w2 = (const float*)d_in[4];
    float* y = (float*)d_out;

    // dynamic smem (bytes): up 36864, down 24576
    int smemUp = (2 * A_STG * 3) * 4;
    int smemDn = (2 * A_STG * 2) * 4;

    cudaFuncSetAttribute(ffn_up_kernel, cudaFuncAttributeMaxDynamicSharedMemorySize, 65536);
    cudaFuncSetAttribute(down_kernel,   cudaFuncAttributeMaxDynamicSharedMemorySize, 65536);

    zero_kernel<<<4096, 256>>>(y, (size_t)T_TOK * D_DIM);

    // fp32 -> fp16 preconversion (hoisted rounding; numerically identical)
    __half* d_xh;  cudaGetSymbolAddress((void**)&d_xh,  g_xh);
    __half* d_w1h; cudaGetSymbolAddress((void**)&d_w1h, g_w1h);
    __half* d_w3h; cudaGetSymbolAddress((void**)&d_w3h, g_w3h);
    __half* d_w2h; cudaGetSymbolAddress((void**)&d_w2h, g_w2h);
    size_t nX = (size_t)T_TOK * D_DIM / 4;
    size_t nW = (size_t)E_NUM * F_DIM * D_DIM / 4;
    convert_kernel<<<2048, 256>>>(x,  d_xh,  nX);
    convert_kernel<<<8192, 256>>>(w1, d_w1h, nW);
    convert_kernel<<<8192, 256>>>(w3, d_w3h, nW);
    convert_kernel<<<8192, 256>>>(w2, d_w2h, nW);

    routing_kernel<<<T_TOK / 8, 256>>>(x, gw);
    scan_kernel<<<1, 32>>>();
    fill_kernel<<<T_TOK / 256, 256>>>();

    dim3 gA(P_MAX / 128, F_DIM / 128, E_NUM);
    ffn_up_kernel<<<gA, 512, smemUp>>>();

    dim3 gB(P_MAX / 128, D_DIM / 128, E_NUM);
    down_kernel<<<gB, 512, smemDn>>>(y);
}